// round 1
// baseline (speedup 1.0000x reference)
#include <cuda_runtime.h>
#include <cuda_bf16.h>
#include <math.h>

// ---------------- problem constants ----------------
#define BATCH 4
#define IMGH  64
#define IMGW  64
#define CDIM  768
#define WS    14
#define TOK   196          // WS*WS
#define NH    12
#define HD    64
#define NWH   5            // ceil(64/14)
#define NWW   5
#define BW    100          // BATCH*NWH*NWW
#define ROWS_WIN 19600     // BW*TOK
#define ROWS_IMG 16384     // BATCH*IMGH*IMGW
#define QKVN  2304
#define FFN   3072

// ---------------- scratch (static device memory; no allocs allowed) ----------------
__device__ float g_win[(size_t)ROWS_WIN * CDIM];   // LN1 + window partition
__device__ float g_qkv[(size_t)ROWS_WIN * QKVN];   // qkv
__device__ float g_att[(size_t)ROWS_WIN * CDIM];   // attention output (token-major, NH*HD cols)
__device__ float g_x2 [(size_t)ROWS_IMG * CDIM];   // after proj + residual
__device__ float g_yln[(size_t)ROWS_IMG * CDIM];   // LN2 output
__device__ float g_y1 [(size_t)ROWS_IMG * FFN];    // fc1+gelu output

// ---------------- LN1 + window partition (warp per window-token row) ----------------
__global__ void ln1_win_kernel(const float* __restrict__ x,
                               const float* __restrict__ g,
                               const float* __restrict__ b,
                               float* __restrict__ out_) {
    int warp = (blockIdx.x * blockDim.x + threadIdx.x) >> 5;
    int lane = threadIdx.x & 31;
    if (warp >= ROWS_WIN) return;
    int r  = warp;
    int bw = r / TOK, t = r % TOK;
    int bb = bw / (NWH * NWW), rem = bw % (NWH * NWW);
    int wh = rem / NWW, ww = rem % NWW;
    int i = t / WS, j = t % WS;
    int h = wh * WS + i, w = ww * WS + j;
    float* out = out_ + (size_t)r * CDIM;
    if (h >= IMGH || w >= IMGW) {
        float4 z = make_float4(0.f, 0.f, 0.f, 0.f);
        #pragma unroll
        for (int q = 0; q < 6; q++) *(float4*)(out + lane * 4 + q * 128) = z;
        return;
    }
    const float* row = x + ((size_t)(bb * IMGH + h) * IMGW + w) * CDIM;
    float v[24];
    float s = 0.f;
    #pragma unroll
    for (int q = 0; q < 6; q++) {
        float4 f = *(const float4*)(row + lane * 4 + q * 128);
        v[q*4+0] = f.x; v[q*4+1] = f.y; v[q*4+2] = f.z; v[q*4+3] = f.w;
        s += f.x + f.y + f.z + f.w;
    }
    #pragma unroll
    for (int o = 16; o > 0; o >>= 1) s += __shfl_xor_sync(0xffffffffu, s, o);
    float mean = s * (1.0f / CDIM);
    float ss = 0.f;
    #pragma unroll
    for (int q = 0; q < 24; q++) { float d = v[q] - mean; ss += d * d; }
    #pragma unroll
    for (int o = 16; o > 0; o >>= 1) ss += __shfl_xor_sync(0xffffffffu, ss, o);
    float rstd = rsqrtf(ss * (1.0f / CDIM) + 1e-6f);
    #pragma unroll
    for (int q = 0; q < 6; q++) {
        int c = lane * 4 + q * 128;
        float4 gg = *(const float4*)(g + c);
        float4 bb4 = *(const float4*)(b + c);
        float4 o4;
        o4.x = (v[q*4+0] - mean) * rstd * gg.x + bb4.x;
        o4.y = (v[q*4+1] - mean) * rstd * gg.y + bb4.y;
        o4.z = (v[q*4+2] - mean) * rstd * gg.z + bb4.z;
        o4.w = (v[q*4+3] - mean) * rstd * gg.w + bb4.w;
        *(float4*)(out + c) = o4;
    }
}

// ---------------- LN2 (warp per row, identity mapping) ----------------
__global__ void ln2_kernel(const float* __restrict__ x,
                           const float* __restrict__ g,
                           const float* __restrict__ b,
                           float* __restrict__ out_) {
    int warp = (blockIdx.x * blockDim.x + threadIdx.x) >> 5;
    int lane = threadIdx.x & 31;
    if (warp >= ROWS_IMG) return;
    const float* row = x + (size_t)warp * CDIM;
    float* out = out_ + (size_t)warp * CDIM;
    float v[24];
    float s = 0.f;
    #pragma unroll
    for (int q = 0; q < 6; q++) {
        float4 f = *(const float4*)(row + lane * 4 + q * 128);
        v[q*4+0] = f.x; v[q*4+1] = f.y; v[q*4+2] = f.z; v[q*4+3] = f.w;
        s += f.x + f.y + f.z + f.w;
    }
    #pragma unroll
    for (int o = 16; o > 0; o >>= 1) s += __shfl_xor_sync(0xffffffffu, s, o);
    float mean = s * (1.0f / CDIM);
    float ss = 0.f;
    #pragma unroll
    for (int q = 0; q < 24; q++) { float d = v[q] - mean; ss += d * d; }
    #pragma unroll
    for (int o = 16; o > 0; o >>= 1) ss += __shfl_xor_sync(0xffffffffu, ss, o);
    float rstd = rsqrtf(ss * (1.0f / CDIM) + 1e-6f);
    #pragma unroll
    for (int q = 0; q < 6; q++) {
        int c = lane * 4 + q * 128;
        float4 gg = *(const float4*)(g + c);
        float4 bb4 = *(const float4*)(b + c);
        float4 o4;
        o4.x = (v[q*4+0] - mean) * rstd * gg.x + bb4.x;
        o4.y = (v[q*4+1] - mean) * rstd * gg.y + bb4.y;
        o4.z = (v[q*4+2] - mean) * rstd * gg.z + bb4.z;
        o4.w = (v[q*4+3] - mean) * rstd * gg.w + bb4.w;
        *(float4*)(out + c) = o4;
    }
}

// ---------------- generic SGEMM, 128x128 tile, 256 threads, 8x8 frags ----------------
// EPI: 0 = bias; 1 = bias+gelu; 2 = bias + window-reverse scatter + residual(R) into C;
//      3 = bias + residual(R) into C (same layout)
template<int EPI>
__global__ __launch_bounds__(256, 2)
void sgemm_kernel(const float* __restrict__ A, const float* __restrict__ B,
                  const float* __restrict__ bias, const float* __restrict__ R,
                  float* __restrict__ Cc, int M, int N, int K) {
    __shared__ float As[16][132];
    __shared__ float Bs[16][128];
    int tid = threadIdx.x;
    int m0 = blockIdx.y * 128, n0 = blockIdx.x * 128;
    int tx = tid & 15, ty = tid >> 4;
    float acc[8][8];
    #pragma unroll
    for (int i = 0; i < 8; i++)
        #pragma unroll
        for (int j = 0; j < 8; j++) acc[i][j] = 0.f;

    int arow = tid >> 2;            // 0..63
    int ak4  = (tid & 3) * 4;       // 0,4,8,12
    int bkr  = tid >> 5;            // 0..7
    int bn4  = (tid & 31) * 4;      // 0..124

    for (int k0 = 0; k0 < K; k0 += 16) {
        #pragma unroll
        for (int p = 0; p < 2; p++) {
            int m = m0 + arow + p * 64;
            float4 f = make_float4(0.f, 0.f, 0.f, 0.f);
            if (m < M) f = *(const float4*)(A + (size_t)m * K + k0 + ak4);
            As[ak4 + 0][arow + p * 64] = f.x;
            As[ak4 + 1][arow + p * 64] = f.y;
            As[ak4 + 2][arow + p * 64] = f.z;
            As[ak4 + 3][arow + p * 64] = f.w;
        }
        #pragma unroll
        for (int p = 0; p < 2; p++) {
            int kk = bkr + p * 8;
            float4 f = *(const float4*)(B + (size_t)(k0 + kk) * N + n0 + bn4);
            *(float4*)(&Bs[kk][bn4]) = f;
        }
        __syncthreads();
        #pragma unroll
        for (int kk = 0; kk < 16; kk++) {
            float a[8], bb[8];
            float4 a0 = *(float4*)(&As[kk][ty * 8]);
            float4 a1 = *(float4*)(&As[kk][ty * 8 + 4]);
            float4 b0 = *(float4*)(&Bs[kk][tx * 8]);
            float4 b1 = *(float4*)(&Bs[kk][tx * 8 + 4]);
            a[0]=a0.x; a[1]=a0.y; a[2]=a0.z; a[3]=a0.w;
            a[4]=a1.x; a[5]=a1.y; a[6]=a1.z; a[7]=a1.w;
            bb[0]=b0.x; bb[1]=b0.y; bb[2]=b0.z; bb[3]=b0.w;
            bb[4]=b1.x; bb[5]=b1.y; bb[6]=b1.z; bb[7]=b1.w;
            #pragma unroll
            for (int i = 0; i < 8; i++)
                #pragma unroll
                for (int j = 0; j < 8; j++)
                    acc[i][j] = fmaf(a[i], bb[j], acc[i][j]);
        }
        __syncthreads();
    }

    // epilogue
    #pragma unroll
    for (int i = 0; i < 8; i++) {
        int m = m0 + ty * 8 + i;
        if (m >= M) continue;
        if (EPI == 2) {
            // window reverse: row m -> (b,h,w), drop padded, add residual
            int bw = m / TOK, t = m % TOK;
            int bb = bw / (NWH * NWW), rem = bw % (NWH * NWW);
            int wh = rem / NWW, ww = rem % NWW;
            int ii = t / WS, jj = t % WS;
            int h = wh * WS + ii, w = ww * WS + jj;
            if (h >= IMGH || w >= IMGW) continue;
            size_t base = ((size_t)(bb * IMGH + h) * IMGW + w) * CDIM;
            #pragma unroll
            for (int j = 0; j < 8; j++) {
                int n = n0 + tx * 8 + j;
                float val = acc[i][j] + bias[n];
                Cc[base + n] = R[base + n] + val;
            }
        } else {
            size_t rowoff = (size_t)m * N;
            #pragma unroll
            for (int j = 0; j < 8; j++) {
                int n = n0 + tx * 8 + j;
                float val = acc[i][j] + bias[n];
                if (EPI == 0) {
                    Cc[rowoff + n] = val;
                } else if (EPI == 1) {
                    Cc[rowoff + n] = 0.5f * val * (1.0f + erff(val * 0.7071067811865476f));
                } else { // EPI == 3
                    Cc[rowoff + n] = R[rowoff + n] + val;
                }
            }
        }
    }
}

// ---------------- windowed attention with decomposed rel-pos bias ----------------
// one CTA per (window, head); 256 threads = 8 warps; warp per query row.
#define SM_QS   0
#define SM_VS   (TOK * 64)
#define SM_KS   (2 * TOK * 64)
#define SM_RH   (2 * TOK * 64 + TOK * 65)
#define SM_RW   (SM_RH + 27 * 65)
#define SM_PS   (SM_RW + 27 * 65)
#define SM_RHW  (SM_PS + 8 * 200)
#define SM_TOTAL_FLOATS (SM_RHW + 8 * 64)

__global__ void attn_kernel(const float* __restrict__ qkv,
                            const float* __restrict__ relh,
                            const float* __restrict__ relw,
                            float* __restrict__ attout) {
    extern __shared__ float sm[];
    float* qs = sm + SM_QS;    // [196][64]
    float* vs = sm + SM_VS;    // [196][64]
    float* ks = sm + SM_KS;    // [196][65]
    float* Rh = sm + SM_RH;    // [27][65]
    float* Rw = sm + SM_RW;    // [27][65]
    float* Ps = sm + SM_PS;    // [8][200]
    float* rhw = sm + SM_RHW;  // [8][64]: [0..13]=rh, [32..45]=rw

    int blk = blockIdx.x;
    int bw = blk / NH, nh = blk % NH;
    int tid = threadIdx.x, lane = tid & 31, warp = tid >> 5;

    const float* base = qkv + (size_t)bw * TOK * QKVN + nh * HD;
    for (int t4 = tid; t4 < TOK * 16; t4 += 256) {
        int t = t4 >> 4, c4 = (t4 & 15) * 4;
        const float* p = base + (size_t)t * QKVN;
        float4 q4 = *(const float4*)(p + c4);
        float4 k4 = *(const float4*)(p + CDIM + c4);
        float4 v4 = *(const float4*)(p + 2 * CDIM + c4);
        *(float4*)(qs + t * 64 + c4) = q4;
        ks[t * 65 + c4 + 0] = k4.x;
        ks[t * 65 + c4 + 1] = k4.y;
        ks[t * 65 + c4 + 2] = k4.z;
        ks[t * 65 + c4 + 3] = k4.w;
        *(float4*)(vs + t * 64 + c4) = v4;
    }
    for (int idx = tid; idx < 27 * 64; idx += 256) {
        int rr = idx >> 6, c = idx & 63;
        Rh[rr * 65 + c] = relh[idx];
        Rw[rr * 65 + c] = relw[idx];
    }
    __syncthreads();

    const float scale = 0.125f;  // 64^-0.5
    for (int qi = warp; qi < TOK; qi += 8) {
        int i = qi / WS, j = qi % WS;
        const float* qrow = qs + qi * 64;

        // decomposed rel-pos dots (lanes 0..13 each do one k/l index)
        float rh = 0.f, rw = 0.f;
        if (lane < WS) {
            const float* rhrow = Rh + (i - lane + WS - 1) * 65;
            const float* rwrow = Rw + (j - lane + WS - 1) * 65;
            #pragma unroll 8
            for (int c = 0; c < 64; c++) {
                float qc = qrow[c];
                rh = fmaf(qc, rhrow[c], rh);
                rw = fmaf(qc, rwrow[c], rw);
            }
        }
        rhw[warp * 64 + lane] = rh;
        rhw[warp * 64 + 32 + lane] = rw;
        __syncwarp();

        // q . k^T for this row (each lane: k = lane + 32m)
        float accv[7];
        #pragma unroll
        for (int m = 0; m < 7; m++) accv[m] = 0.f;
        #pragma unroll 4
        for (int c = 0; c < 64; c++) {
            float qc = qrow[c];
            #pragma unroll
            for (int m = 0; m < 7; m++) {
                int kj = lane + 32 * m;
                if (kj < TOK) accv[m] = fmaf(qc, ks[kj * 65 + c], accv[m]);
            }
        }
        float s[7];
        #pragma unroll
        for (int m = 0; m < 7; m++) {
            int kj = lane + 32 * m;
            if (kj < TOK) {
                int kk = kj / WS, ll = kj % WS;
                s[m] = accv[m] * scale + rhw[warp * 64 + kk] + rhw[warp * 64 + 32 + ll];
            } else {
                s[m] = -1e30f;
            }
        }
        // softmax across the 196 entries held by the warp
        float mx = -1e30f;
        #pragma unroll
        for (int m = 0; m < 7; m++) mx = fmaxf(mx, s[m]);
        #pragma unroll
        for (int o = 16; o > 0; o >>= 1) mx = fmaxf(mx, __shfl_xor_sync(0xffffffffu, mx, o));
        float p[7], sum = 0.f;
        #pragma unroll
        for (int m = 0; m < 7; m++) { p[m] = __expf(s[m] - mx); sum += p[m]; }
        #pragma unroll
        for (int o = 16; o > 0; o >>= 1) sum += __shfl_xor_sync(0xffffffffu, sum, o);
        float inv = __frcp_rn(sum);
        #pragma unroll
        for (int m = 0; m < 7; m++) {
            int kj = lane + 32 * m;
            if (kj < TOK) Ps[warp * 200 + kj] = p[m] * inv;
        }
        __syncwarp();

        // P . V : lane owns channels (lane, lane+32)
        float o0 = 0.f, o1 = 0.f;
        #pragma unroll 4
        for (int kj = 0; kj < TOK; kj++) {
            float pp = Ps[warp * 200 + kj];
            o0 = fmaf(pp, vs[kj * 64 + lane], o0);
            o1 = fmaf(pp, vs[kj * 64 + 32 + lane], o1);
        }
        float* orow = attout + ((size_t)(bw * TOK + qi)) * CDIM + nh * HD;
        orow[lane] = o0;
        orow[lane + 32] = o1;
        __syncwarp();
    }
}

// ---------------- launch ----------------
extern "C" void kernel_launch(void* const* d_in, const int* in_sizes, int n_in,
                              void* d_out, int out_size) {
    const float* x       = (const float*)d_in[0];
    const float* ln1_g   = (const float*)d_in[1];
    const float* ln1_b   = (const float*)d_in[2];
    const float* w_qkv   = (const float*)d_in[3];
    const float* b_qkv   = (const float*)d_in[4];
    const float* w_proj  = (const float*)d_in[5];
    const float* b_proj  = (const float*)d_in[6];
    const float* relh    = (const float*)d_in[7];
    const float* relw    = (const float*)d_in[8];
    const float* ln2_g   = (const float*)d_in[9];
    const float* ln2_b   = (const float*)d_in[10];
    const float* w_fc1   = (const float*)d_in[11];
    const float* b_fc1   = (const float*)d_in[12];
    const float* w_fc2   = (const float*)d_in[13];
    const float* b_fc2   = (const float*)d_in[14];
    float* out = (float*)d_out;

    float *win, *qkv, *att, *x2, *yln, *y1;
    cudaGetSymbolAddress((void**)&win, g_win);
    cudaGetSymbolAddress((void**)&qkv, g_qkv);
    cudaGetSymbolAddress((void**)&att, g_att);
    cudaGetSymbolAddress((void**)&x2,  g_x2);
    cudaGetSymbolAddress((void**)&yln, g_yln);
    cudaGetSymbolAddress((void**)&y1,  g_y1);

    const int smem_attn = SM_TOTAL_FLOATS * 4;
    cudaFuncSetAttribute(attn_kernel, cudaFuncAttributeMaxDynamicSharedMemorySize, smem_attn);

    // 1) LN1 + window partition -> g_win [19600, 768]
    ln1_win_kernel<<<(ROWS_WIN * 32 + 255) / 256, 256>>>(x, ln1_g, ln1_b, win);

    // 2) QKV GEMM: [19600,768] x [768,2304]
    sgemm_kernel<0><<<dim3(QKVN / 128, (ROWS_WIN + 127) / 128), 256>>>(
        win, w_qkv, b_qkv, nullptr, qkv, ROWS_WIN, QKVN, CDIM);

    // 3) attention (1200 head-windows)
    attn_kernel<<<BW * NH, 256, smem_attn>>>(qkv, relh, relw, att);

    // 4) proj GEMM + window reverse + residual -> g_x2 [16384,768]
    sgemm_kernel<2><<<dim3(CDIM / 128, (ROWS_WIN + 127) / 128), 256>>>(
        att, w_proj, b_proj, x, x2, ROWS_WIN, CDIM, CDIM);

    // 5) LN2 -> g_yln
    ln2_kernel<<<(ROWS_IMG * 32 + 255) / 256, 256>>>(x2, ln2_g, ln2_b, yln);

    // 6) fc1 + gelu: [16384,768] x [768,3072]
    sgemm_kernel<1><<<dim3(FFN / 128, ROWS_IMG / 128), 256>>>(
        yln, w_fc1, b_fc1, nullptr, y1, ROWS_IMG, FFN, CDIM);

    // 7) fc2 + residual: [16384,3072] x [3072,768] -> d_out
    sgemm_kernel<3><<<dim3(CDIM / 128, ROWS_IMG / 128), 256>>>(
        y1, w_fc2, b_fc2, x2, out, ROWS_IMG, CDIM, FFN);
}

// round 2
// speedup vs baseline: 2.2438x; 2.2438x over previous
#include <cuda_runtime.h>
#include <cuda_bf16.h>
#include <math.h>
#include <stdint.h>

// ---------------- problem constants ----------------
#define BATCH 4
#define IMGH  64
#define IMGW  64
#define CDIM  768
#define WS    14
#define TOK   196
#define NH    12
#define HD    64
#define NWH   5
#define NWW   5
#define BW    100
#define ROWS_WIN 19600
#define ROWS_IMG 16384
#define QKVN  2304
#define FFN   3072

// ---------------- scratch ----------------
__device__ float g_win[(size_t)ROWS_WIN * CDIM];
__device__ float g_qkv[(size_t)ROWS_WIN * QKVN];
__device__ float g_att[(size_t)ROWS_WIN * CDIM];
__device__ float g_x2 [(size_t)ROWS_IMG * CDIM];
__device__ float g_yln[(size_t)ROWS_IMG * CDIM];
__device__ float g_y1 [(size_t)ROWS_IMG * FFN];
__device__ float g_wqkv[(size_t)CDIM * QKVN];
__device__ float g_wproj[(size_t)CDIM * CDIM];
__device__ float g_wfc1[(size_t)CDIM * FFN];
__device__ float g_wfc2[(size_t)FFN * CDIM];

// ---------------- helpers ----------------
__device__ __forceinline__ float tf32r(float x) {
    uint32_t u;
    asm("cvt.rna.tf32.f32 %0, %1;" : "=r"(u) : "f"(x));
    return __uint_as_float(u);
}

__device__ __forceinline__ void cp16(float* sdst, const float* gsrc, int bytes) {
    uint32_t sa = (uint32_t)__cvta_generic_to_shared(sdst);
    asm volatile("cp.async.cg.shared.global [%0], [%1], 16, %2;"
                 :: "r"(sa), "l"(gsrc), "r"(bytes));
}

__device__ __forceinline__ void mma_tf32(float c[4], const uint32_t a[4], const uint32_t b[2]) {
    asm volatile(
        "mma.sync.aligned.m16n8k8.row.col.f32.tf32.tf32.f32 "
        "{%0,%1,%2,%3}, {%4,%5,%6,%7}, {%8,%9}, {%0,%1,%2,%3};"
        : "+f"(c[0]), "+f"(c[1]), "+f"(c[2]), "+f"(c[3])
        : "r"(a[0]), "r"(a[1]), "r"(a[2]), "r"(a[3]), "r"(b[0]), "r"(b[1]));
}

// ---------------- weight rounding ----------------
__global__ void round_tf32_kernel(const float* __restrict__ in, float* __restrict__ out, int n4) {
    int i = blockIdx.x * blockDim.x + threadIdx.x;
    if (i >= n4) return;
    float4 f = ((const float4*)in)[i];
    f.x = tf32r(f.x); f.y = tf32r(f.y); f.z = tf32r(f.z); f.w = tf32r(f.w);
    ((float4*)out)[i] = f;
}

// ---------------- LN1 + window partition ----------------
__global__ void ln1_win_kernel(const float* __restrict__ x,
                               const float* __restrict__ g,
                               const float* __restrict__ b,
                               float* __restrict__ out_) {
    int warp = (blockIdx.x * blockDim.x + threadIdx.x) >> 5;
    int lane = threadIdx.x & 31;
    if (warp >= ROWS_WIN) return;
    int r  = warp;
    int bw = r / TOK, t = r % TOK;
    int bb = bw / (NWH * NWW), rem = bw % (NWH * NWW);
    int wh = rem / NWW, ww = rem % NWW;
    int i = t / WS, j = t % WS;
    int h = wh * WS + i, w = ww * WS + j;
    float* out = out_ + (size_t)r * CDIM;
    if (h >= IMGH || w >= IMGW) {
        float4 z = make_float4(0.f, 0.f, 0.f, 0.f);
        #pragma unroll
        for (int q = 0; q < 6; q++) *(float4*)(out + lane * 4 + q * 128) = z;
        return;
    }
    const float* row = x + ((size_t)(bb * IMGH + h) * IMGW + w) * CDIM;
    float v[24];
    float s = 0.f;
    #pragma unroll
    for (int q = 0; q < 6; q++) {
        float4 f = *(const float4*)(row + lane * 4 + q * 128);
        v[q*4+0] = f.x; v[q*4+1] = f.y; v[q*4+2] = f.z; v[q*4+3] = f.w;
        s += f.x + f.y + f.z + f.w;
    }
    #pragma unroll
    for (int o = 16; o > 0; o >>= 1) s += __shfl_xor_sync(0xffffffffu, s, o);
    float mean = s * (1.0f / CDIM);
    float ss = 0.f;
    #pragma unroll
    for (int q = 0; q < 24; q++) { float d = v[q] - mean; ss += d * d; }
    #pragma unroll
    for (int o = 16; o > 0; o >>= 1) ss += __shfl_xor_sync(0xffffffffu, ss, o);
    float rstd = rsqrtf(ss * (1.0f / CDIM) + 1e-6f);
    #pragma unroll
    for (int q = 0; q < 6; q++) {
        int c = lane * 4 + q * 128;
        float4 gg = *(const float4*)(g + c);
        float4 bb4 = *(const float4*)(b + c);
        float4 o4;
        o4.x = tf32r((v[q*4+0] - mean) * rstd * gg.x + bb4.x);
        o4.y = tf32r((v[q*4+1] - mean) * rstd * gg.y + bb4.y);
        o4.z = tf32r((v[q*4+2] - mean) * rstd * gg.z + bb4.z);
        o4.w = tf32r((v[q*4+3] - mean) * rstd * gg.w + bb4.w);
        *(float4*)(out + c) = o4;
    }
}

// ---------------- LN2 ----------------
__global__ void ln2_kernel(const float* __restrict__ x,
                           const float* __restrict__ g,
                           const float* __restrict__ b,
                           float* __restrict__ out_) {
    int warp = (blockIdx.x * blockDim.x + threadIdx.x) >> 5;
    int lane = threadIdx.x & 31;
    if (warp >= ROWS_IMG) return;
    const float* row = x + (size_t)warp * CDIM;
    float* out = out_ + (size_t)warp * CDIM;
    float v[24];
    float s = 0.f;
    #pragma unroll
    for (int q = 0; q < 6; q++) {
        float4 f = *(const float4*)(row + lane * 4 + q * 128);
        v[q*4+0] = f.x; v[q*4+1] = f.y; v[q*4+2] = f.z; v[q*4+3] = f.w;
        s += f.x + f.y + f.z + f.w;
    }
    #pragma unroll
    for (int o = 16; o > 0; o >>= 1) s += __shfl_xor_sync(0xffffffffu, s, o);
    float mean = s * (1.0f / CDIM);
    float ss = 0.f;
    #pragma unroll
    for (int q = 0; q < 24; q++) { float d = v[q] - mean; ss += d * d; }
    #pragma unroll
    for (int o = 16; o > 0; o >>= 1) ss += __shfl_xor_sync(0xffffffffu, ss, o);
    float rstd = rsqrtf(ss * (1.0f / CDIM) + 1e-6f);
    #pragma unroll
    for (int q = 0; q < 6; q++) {
        int c = lane * 4 + q * 128;
        float4 gg = *(const float4*)(g + c);
        float4 bb4 = *(const float4*)(b + c);
        float4 o4;
        o4.x = tf32r((v[q*4+0] - mean) * rstd * gg.x + bb4.x);
        o4.y = tf32r((v[q*4+1] - mean) * rstd * gg.y + bb4.y);
        o4.z = tf32r((v[q*4+2] - mean) * rstd * gg.z + bb4.z);
        o4.w = tf32r((v[q*4+3] - mean) * rstd * gg.w + bb4.w);
        *(float4*)(out + c) = o4;
    }
}

// ---------------- TF32 tensor-core GEMM ----------------
// 128x128x32 tiles, 256 threads, warps 2(M)x4(N), warp tile 64x32, m16n8k8.
// EPI: 0=bias; 1=bias+gelu(+tf32 round); 2=bias+window-reverse scatter+residual; 3=bias+residual
#define AS_STRIDE 36
#define BS_STRIDE 132
#define AS_FLOATS (128 * AS_STRIDE)          // per stage
#define BS_FLOATS (32 * BS_STRIDE)
#define GEMM_SMEM ((2 * AS_FLOATS + 2 * BS_FLOATS) * 4)

template<int EPI>
__global__ __launch_bounds__(256, 2)
void tgemm(const float* __restrict__ A, const float* __restrict__ B,
           const float* __restrict__ bias, const float* __restrict__ R,
           float* __restrict__ Cc, int M, int N, int K) {
    extern __shared__ float sm[];
    float* As = sm;                       // [2][128][36]
    float* Bs = sm + 2 * AS_FLOATS;       // [2][32][132]

    int tid = threadIdx.x;
    int warp = tid >> 5, lane = tid & 31;
    int g = lane >> 2, c = lane & 3;
    int warpM = warp >> 2, warpN = warp & 3;
    int mw = warpM * 64, nw = warpN * 32;
    int m0 = blockIdx.y * 128, n0 = blockIdx.x * 128;

    float acc[4][4][4];
    #pragma unroll
    for (int i = 0; i < 4; i++)
        #pragma unroll
        for (int j = 0; j < 4; j++)
            #pragma unroll
            for (int q = 0; q < 4; q++) acc[i][j][q] = 0.f;

    int arow = tid >> 3;        // 0..31
    int aseg = (tid & 7) * 4;   // k offset
    int brow = tid >> 5;        // 0..7 (wait: 1024 chunks / 256 threads, row = chunk>>5)
    int bcol = (tid & 31) * 4;

    auto loadA = [&](int stage, int k0) {
        float* dst = As + stage * AS_FLOATS;
        #pragma unroll
        for (int i = 0; i < 4; i++) {
            int mrel = arow + i * 32;
            int m = m0 + mrel;
            bool v = m < M;
            const float* src = v ? (A + (size_t)m * K + k0 + aseg) : A;
            cp16(dst + mrel * AS_STRIDE + aseg, src, v ? 16 : 0);
        }
    };
    auto loadB = [&](int stage, int k0) {
        float* dst = Bs + stage * BS_FLOATS;
        #pragma unroll
        for (int i = 0; i < 4; i++) {
            int krel = brow + i * 8;
            cp16(dst + krel * BS_STRIDE + bcol,
                 B + (size_t)(k0 + krel) * N + n0 + bcol, 16);
        }
    };

    int nk = K / 32;
    loadA(0, 0); loadB(0, 0);
    asm volatile("cp.async.commit_group;");

    for (int t = 0; t < nk; t++) {
        asm volatile("cp.async.wait_group 0;" ::: "memory");
        __syncthreads();
        if (t + 1 < nk) {
            loadA((t + 1) & 1, (t + 1) * 32);
            loadB((t + 1) & 1, (t + 1) * 32);
            asm volatile("cp.async.commit_group;");
        }
        const float* a_s = As + (t & 1) * AS_FLOATS;
        const float* b_s = Bs + (t & 1) * BS_FLOATS;
        #pragma unroll
        for (int kk = 0; kk < 4; kk++) {
            int kb = kk * 8;
            uint32_t af[4][4], bf[4][2];
            #pragma unroll
            for (int tm = 0; tm < 4; tm++) {
                const float* ap = a_s + (mw + tm * 16 + g) * AS_STRIDE + kb;
                af[tm][0] = __float_as_uint(ap[c]);
                af[tm][1] = __float_as_uint(ap[8 * AS_STRIDE + c]);
                af[tm][2] = __float_as_uint(ap[c + 4]);
                af[tm][3] = __float_as_uint(ap[8 * AS_STRIDE + c + 4]);
            }
            #pragma unroll
            for (int tn = 0; tn < 4; tn++) {
                const float* bp = b_s + (kb + c) * BS_STRIDE + nw + tn * 8 + g;
                bf[tn][0] = __float_as_uint(bp[0]);
                bf[tn][1] = __float_as_uint(bp[4 * BS_STRIDE]);
            }
            #pragma unroll
            for (int tm = 0; tm < 4; tm++)
                #pragma unroll
                for (int tn = 0; tn < 4; tn++)
                    mma_tf32(acc[tm][tn], af[tm], bf[tn]);
        }
        __syncthreads();
    }

    // epilogue
    #pragma unroll
    for (int tm = 0; tm < 4; tm++) {
        #pragma unroll
        for (int half = 0; half < 2; half++) {
            int m = m0 + mw + tm * 16 + g + half * 8;
            if (m >= M) continue;
            size_t obase;
            const float* rbase = nullptr;
            bool valid = true;
            if (EPI == 2) {
                int bw = m / TOK, tt = m % TOK;
                int bb = bw / (NWH * NWW), rem = bw % (NWH * NWW);
                int wh = rem / NWW, ww = rem % NWW;
                int ii = tt / WS, jj = tt % WS;
                int h = wh * WS + ii, w = ww * WS + jj;
                if (h >= IMGH || w >= IMGW) valid = false;
                else {
                    obase = ((size_t)(bb * IMGH + h) * IMGW + w) * CDIM;
                    rbase = R + obase;
                }
            } else {
                obase = (size_t)m * N;
                if (EPI == 3) rbase = R + obase;
            }
            if (!valid) continue;
            #pragma unroll
            for (int tn = 0; tn < 4; tn++) {
                int col = nw + tn * 8 + 2 * c;
                int n = n0 + col;
                float v0 = acc[tm][tn][half * 2 + 0] + bias[n];
                float v1 = acc[tm][tn][half * 2 + 1] + bias[n + 1];
                if (EPI == 1) {
                    v0 = tf32r(0.5f * v0 * (1.0f + erff(v0 * 0.7071067811865476f)));
                    v1 = tf32r(0.5f * v1 * (1.0f + erff(v1 * 0.7071067811865476f)));
                } else if (EPI == 2 || EPI == 3) {
                    v0 += rbase[n];
                    v1 += rbase[n + 1];
                }
                float2 o2 = make_float2(v0, v1);
                *(float2*)(Cc + obase + n) = o2;
            }
        }
    }
}

// ---------------- windowed attention ----------------
#define SM_QS   0
#define SM_VS   (TOK * 64)
#define SM_KS   (2 * TOK * 64)
#define SM_RH   (2 * TOK * 64 + TOK * 65)
#define SM_RW   (SM_RH + 27 * 65)
#define SM_PS   (SM_RW + 27 * 65)
#define SM_RHW  (SM_PS + 8 * 200)
#define SM_TOTAL_FLOATS (SM_RHW + 8 * 64)

__global__ void attn_kernel(const float* __restrict__ qkv,
                            const float* __restrict__ relh,
                            const float* __restrict__ relw,
                            float* __restrict__ attout) {
    extern __shared__ float sm[];
    float* qs = sm + SM_QS;
    float* vs = sm + SM_VS;
    float* ks = sm + SM_KS;
    float* Rh = sm + SM_RH;
    float* Rw = sm + SM_RW;
    float* Ps = sm + SM_PS;
    float* rhw = sm + SM_RHW;

    int blk = blockIdx.x;
    int bw = blk / NH, nh = blk % NH;
    int tid = threadIdx.x, lane = tid & 31, warp = tid >> 5;

    const float* base = qkv + (size_t)bw * TOK * QKVN + nh * HD;
    for (int t4 = tid; t4 < TOK * 16; t4 += 256) {
        int t = t4 >> 4, c4 = (t4 & 15) * 4;
        const float* p = base + (size_t)t * QKVN;
        float4 q4 = *(const float4*)(p + c4);
        float4 k4 = *(const float4*)(p + CDIM + c4);
        float4 v4 = *(const float4*)(p + 2 * CDIM + c4);
        *(float4*)(qs + t * 64 + c4) = q4;
        ks[t * 65 + c4 + 0] = k4.x;
        ks[t * 65 + c4 + 1] = k4.y;
        ks[t * 65 + c4 + 2] = k4.z;
        ks[t * 65 + c4 + 3] = k4.w;
        *(float4*)(vs + t * 64 + c4) = v4;
    }
    for (int idx = tid; idx < 27 * 64; idx += 256) {
        int rr = idx >> 6, c = idx & 63;
        Rh[rr * 65 + c] = relh[idx];
        Rw[rr * 65 + c] = relw[idx];
    }
    __syncthreads();

    const float scale = 0.125f;
    for (int qi = warp; qi < TOK; qi += 8) {
        int i = qi / WS, j = qi % WS;
        const float* qrow = qs + qi * 64;

        float rh = 0.f, rw = 0.f;
        if (lane < WS) {
            const float* rhrow = Rh + (i - lane + WS - 1) * 65;
            const float* rwrow = Rw + (j - lane + WS - 1) * 65;
            #pragma unroll 8
            for (int c = 0; c < 64; c++) {
                float qc = qrow[c];
                rh = fmaf(qc, rhrow[c], rh);
                rw = fmaf(qc, rwrow[c], rw);
            }
        }
        rhw[warp * 64 + lane] = rh;
        rhw[warp * 64 + 32 + lane] = rw;
        __syncwarp();

        float accv[7];
        #pragma unroll
        for (int m = 0; m < 7; m++) accv[m] = 0.f;
        #pragma unroll 4
        for (int c = 0; c < 64; c++) {
            float qc = qrow[c];
            #pragma unroll
            for (int m = 0; m < 7; m++) {
                int kj = lane + 32 * m;
                if (kj < TOK) accv[m] = fmaf(qc, ks[kj * 65 + c], accv[m]);
            }
        }
        float s[7];
        #pragma unroll
        for (int m = 0; m < 7; m++) {
            int kj = lane + 32 * m;
            if (kj < TOK) {
                int kk = kj / WS, ll = kj % WS;
                s[m] = accv[m] * scale + rhw[warp * 64 + kk] + rhw[warp * 64 + 32 + ll];
            } else {
                s[m] = -1e30f;
            }
        }
        float mx = -1e30f;
        #pragma unroll
        for (int m = 0; m < 7; m++) mx = fmaxf(mx, s[m]);
        #pragma unroll
        for (int o = 16; o > 0; o >>= 1) mx = fmaxf(mx, __shfl_xor_sync(0xffffffffu, mx, o));
        float p[7], sum = 0.f;
        #pragma unroll
        for (int m = 0; m < 7; m++) { p[m] = __expf(s[m] - mx); sum += p[m]; }
        #pragma unroll
        for (int o = 16; o > 0; o >>= 1) sum += __shfl_xor_sync(0xffffffffu, sum, o);
        float inv = __frcp_rn(sum);
        #pragma unroll
        for (int m = 0; m < 7; m++) {
            int kj = lane + 32 * m;
            if (kj < TOK) Ps[warp * 200 + kj] = p[m] * inv;
        }
        __syncwarp();

        float o0 = 0.f, o1 = 0.f;
        #pragma unroll 4
        for (int kj = 0; kj < TOK; kj++) {
            float pp = Ps[warp * 200 + kj];
            o0 = fmaf(pp, vs[kj * 64 + lane], o0);
            o1 = fmaf(pp, vs[kj * 64 + 32 + lane], o1);
        }
        float* orow = attout + ((size_t)(bw * TOK + qi)) * CDIM + nh * HD;
        orow[lane] = tf32r(o0);
        orow[lane + 32] = tf32r(o1);
        __syncwarp();
    }
}

// ---------------- launch ----------------
extern "C" void kernel_launch(void* const* d_in, const int* in_sizes, int n_in,
                              void* d_out, int out_size) {
    const float* x       = (const float*)d_in[0];
    const float* ln1_g   = (const float*)d_in[1];
    const float* ln1_b   = (const float*)d_in[2];
    const float* w_qkv   = (const float*)d_in[3];
    const float* b_qkv   = (const float*)d_in[4];
    const float* w_proj  = (const float*)d_in[5];
    const float* b_proj  = (const float*)d_in[6];
    const float* relh    = (const float*)d_in[7];
    const float* relw    = (const float*)d_in[8];
    const float* ln2_g   = (const float*)d_in[9];
    const float* ln2_b   = (const float*)d_in[10];
    const float* w_fc1   = (const float*)d_in[11];
    const float* b_fc1   = (const float*)d_in[12];
    const float* w_fc2   = (const float*)d_in[13];
    const float* b_fc2   = (const float*)d_in[14];
    float* out = (float*)d_out;

    float *win, *qkv, *att, *x2, *yln, *y1, *wqkv, *wproj, *wfc1, *wfc2;
    cudaGetSymbolAddress((void**)&win, g_win);
    cudaGetSymbolAddress((void**)&qkv, g_qkv);
    cudaGetSymbolAddress((void**)&att, g_att);
    cudaGetSymbolAddress((void**)&x2,  g_x2);
    cudaGetSymbolAddress((void**)&yln, g_yln);
    cudaGetSymbolAddress((void**)&y1,  g_y1);
    cudaGetSymbolAddress((void**)&wqkv,  g_wqkv);
    cudaGetSymbolAddress((void**)&wproj, g_wproj);
    cudaGetSymbolAddress((void**)&wfc1,  g_wfc1);
    cudaGetSymbolAddress((void**)&wfc2,  g_wfc2);

    const int smem_attn = SM_TOTAL_FLOATS * 4;
    cudaFuncSetAttribute(attn_kernel, cudaFuncAttributeMaxDynamicSharedMemorySize, smem_attn);
    cudaFuncSetAttribute(tgemm<0>, cudaFuncAttributeMaxDynamicSharedMemorySize, GEMM_SMEM);
    cudaFuncSetAttribute(tgemm<1>, cudaFuncAttributeMaxDynamicSharedMemorySize, GEMM_SMEM);
    cudaFuncSetAttribute(tgemm<2>, cudaFuncAttributeMaxDynamicSharedMemorySize, GEMM_SMEM);
    cudaFuncSetAttribute(tgemm<3>, cudaFuncAttributeMaxDynamicSharedMemorySize, GEMM_SMEM);

    // round weights to tf32 (once per launch)
    round_tf32_kernel<<<(CDIM * QKVN / 4 + 255) / 256, 256>>>(w_qkv, wqkv, CDIM * QKVN / 4);
    round_tf32_kernel<<<(CDIM * CDIM / 4 + 255) / 256, 256>>>(w_proj, wproj, CDIM * CDIM / 4);
    round_tf32_kernel<<<(CDIM * FFN / 4 + 255) / 256, 256>>>(w_fc1, wfc1, CDIM * FFN / 4);
    round_tf32_kernel<<<(FFN * CDIM / 4 + 255) / 256, 256>>>(w_fc2, wfc2, FFN * CDIM / 4);

    // 1) LN1 + window partition (tf32-rounded output)
    ln1_win_kernel<<<(ROWS_WIN * 32 + 255) / 256, 256>>>(x, ln1_g, ln1_b, win);

    // 2) QKV GEMM
    tgemm<0><<<dim3(QKVN / 128, (ROWS_WIN + 127) / 128), 256, GEMM_SMEM>>>(
        win, wqkv, b_qkv, nullptr, qkv, ROWS_WIN, QKVN, CDIM);

    // 3) attention
    attn_kernel<<<BW * NH, 256, smem_attn>>>(qkv, relh, relw, att);

    // 4) proj + window reverse + residual
    tgemm<2><<<dim3(CDIM / 128, (ROWS_WIN + 127) / 128), 256, GEMM_SMEM>>>(
        att, wproj, b_proj, x, x2, ROWS_WIN, CDIM, CDIM);

    // 5) LN2
    ln2_kernel<<<(ROWS_IMG * 32 + 255) / 256, 256>>>(x2, ln2_g, ln2_b, yln);

    // 6) fc1 + gelu
    tgemm<1><<<dim3(FFN / 128, ROWS_IMG / 128), 256, GEMM_SMEM>>>(
        yln, wfc1, b_fc1, nullptr, y1, ROWS_IMG, FFN, CDIM);

    // 7) fc2 + residual
    tgemm<3><<<dim3(CDIM / 128, ROWS_IMG / 128), 256, GEMM_SMEM>>>(
        y1, wfc2, b_fc2, x2, out, ROWS_IMG, CDIM, FFN);
}